// round 16
// baseline (speedup 1.0000x reference)
#include <cuda_runtime.h>
#include <cuda_bf16.h>
#include <cuda_fp16.h>
#include <cstdint>

// ---------------------------------------------------------------------------
// GraphSAGE persistent mega-kernel with warp-specialized agg/GEMM pipeline.
//  P0 init -> P1 edge hist -> P2 scan | x->fp16 + W prep -> P3 scan fixup
//  -> P4 fill -> P5 pipelined agg+gemm L0 -> P6 bn+relu->fp16
//  -> P7 pipelined agg+gemm L1 -> P8 bn+relu+linear[128,2] -> out
// Fused phase: 32-row x 128-col tiles from an atomic queue. W (bf16 hi+lo,
// full K=256) resident in 128KB smem per layer. A double-buffered (2x32KB):
// warps 16-31 gather tile t+1 (mean of fp16 neighbor rows, dual-ended walk,
// bf16 hi/lo split into SW128 smem) WHILE warps 0-15 run the mma.sync
// mainloop + epilogue (bias, fp32 store, fused BN stats) on tile t.
// ---------------------------------------------------------------------------

#define MAXN 50000
#define MAXE 1048576
#define NB 148
#define NT 1024

__device__ float g_hpre[MAXN * 128];
__device__ __half g_xhalf[MAXN * 128];
__device__ __half g_hhalf[MAXN * 128];
__device__ __nv_bfloat16 g_wth [2][128 * 256];
__device__ __nv_bfloat16 g_wtl [2][128 * 256];
__device__ int   g_deg   [MAXN];
__device__ int   g_rowptr[MAXN + 1];
__device__ int   g_cursor[MAXN];
__device__ int   g_src   [MAXE];
__device__ int   g_dst   [MAXE];
__device__ int   g_ssort [MAXE];
__device__ int   g_bsum  [32];
__device__ float g_stats0[256];
__device__ float g_stats1[256];
__device__ int   g_tile0, g_tile1;
__device__ int   g_is64;
__device__ int   g_barc = 0;
__device__ volatile int g_barp = 0;

// ---------------- helpers ----------------
__device__ __forceinline__ uint32_t s2u(const void* p) {
    uint32_t a;
    asm("{ .reg .u64 t; cvta.to.shared.u64 t, %1; cvt.u32.u64 %0, t; }"
        : "=r"(a) : "l"(p));
    return a;
}
__device__ __forceinline__ void ldm4(uint32_t* r, uint32_t addr) {
    asm volatile("ldmatrix.sync.aligned.m8n8.x4.shared.b16 {%0,%1,%2,%3}, [%4];"
        : "=r"(r[0]), "=r"(r[1]), "=r"(r[2]), "=r"(r[3]) : "r"(addr));
}
__device__ __forceinline__ void mma16816(float* d, const uint32_t* a,
                                         uint32_t b0, uint32_t b1) {
    asm volatile(
        "mma.sync.aligned.m16n8k16.row.col.f32.bf16.bf16.f32 "
        "{%0,%1,%2,%3}, {%4,%5,%6,%7}, {%8,%9}, {%0,%1,%2,%3};"
        : "+f"(d[0]), "+f"(d[1]), "+f"(d[2]), "+f"(d[3])
        : "r"(a[0]), "r"(a[1]), "r"(a[2]), "r"(a[3]), "r"(b0), "r"(b1));
}
__device__ __forceinline__ uint32_t pkbf(float a, float b) {
    __nv_bfloat162 h = __halves2bfloat162(__float2bfloat16(a), __float2bfloat16(b));
    return *(uint32_t*)&h;
}

// grid-wide barrier (all NB blocks resident by construction)
__device__ __forceinline__ void gsync() {
    __syncthreads();
    if (threadIdx.x == 0) {
        __threadfence();
        int gen = g_barp;
        if (atomicAdd(&g_barc, 1) == (int)gridDim.x - 1) {
            g_barc = 0;
            __threadfence();
            g_barp = gen + 1;
        } else {
            while (g_barp == gen) __nanosleep(32);
            __threadfence();
        }
    }
    __syncthreads();
}

// BN finalize from raw stats into smem scale/shift
__device__ __forceinline__ void finalize_smem(
        const float* __restrict__ stats, const float* __restrict__ gamma,
        const float* __restrict__ beta, int n, float* s_sc, float* s_sh) {
    int t = threadIdx.x;
    if (t < 128) {
        float invn = 1.0f / (float)n;
        float mu  = __ldcg(&stats[t]) * invn;
        float var = fmaxf(__ldcg(&stats[128 + t]) * invn - mu * mu, 0.f);
        float rs  = rsqrtf(var + 1e-5f);
        float sc  = __ldg(&gamma[t]) * rs;
        s_sc[t] = sc;
        s_sh[t] = __ldg(&beta[t]) - mu * sc;
    }
    __syncthreads();
}

// smem layout (dynamic):
// A: 2 buffers x (hi 16KB [4 sec x 32r x 128B] + lo 16KB) = 65536
// W: hi 64KB [4 sec x 128n x 128B] + lo 64KB               = 131072
#define SM_A  0
#define SM_W  65536
#define SM_TOTAL 196608

// ---------------- producer: gather+split one 32-row A tile ----------------
__device__ __forceinline__ void fill_tile(
    int p, int row0, int layer, int use_x, const float* __restrict__ xext,
    const float* s_sc, const float* s_sh, char* smem, int n)
{
    int tidl = threadIdx.x - 512;        // 0..511 (warps 16-31)
    int hw = tidl >> 4, lane16 = tidl & 15;
    const uint4* gin4 = (const uint4*)(layer ? g_hhalf : g_xhalf);
    char* buf = smem + SM_A + p * 32768;

    // gather cols 0..127: 1 node row per half-warp, dual-ended edge walk
    {
        int r = hw;                      // 0..31
        int node = row0 + r;
        float acc[8] = {0.f, 0.f, 0.f, 0.f, 0.f, 0.f, 0.f, 0.f};
        if (node < n) {
            int e0 = __ldcg(&g_rowptr[node]);
            int e1 = __ldcg(&g_rowptr[node + 1]);
            int ef = e0, eb = e1 - 1;
            #pragma unroll 2
            for (; ef < eb; ef++, eb--) {
                int sa = __ldg(&g_ssort[ef]);
                int sb2 = __ldg(&g_ssort[eb]);
                uint4 pa = __ldg(&gin4[sa * 16 + lane16]);
                uint4 pb = __ldg(&gin4[sb2 * 16 + lane16]);
                const __half2* ha = (const __half2*)&pa;
                const __half2* hb = (const __half2*)&pb;
                #pragma unroll
                for (int q = 0; q < 4; q++) {
                    float2 fa = __half22float2(ha[q]);
                    float2 fb = __half22float2(hb[q]);
                    acc[2 * q]     += fa.x + fb.x;
                    acc[2 * q + 1] += fa.y + fb.y;
                }
            }
            if (ef == eb) {
                int sa = __ldg(&g_ssort[ef]);
                uint4 pa = __ldg(&gin4[sa * 16 + lane16]);
                const __half2* ha = (const __half2*)&pa;
                #pragma unroll
                for (int q = 0; q < 4; q++) {
                    float2 fa = __half22float2(ha[q]);
                    acc[2 * q]     += fa.x;
                    acc[2 * q + 1] += fa.y;
                }
            }
            float inv = 1.0f / fmaxf((float)(e1 - e0), 1.0f);
            #pragma unroll
            for (int q = 0; q < 8; q++) acc[q] *= inv;
        }
        uint4 hi = make_uint4(pkbf(acc[0], acc[1]), pkbf(acc[2], acc[3]),
                              pkbf(acc[4], acc[5]), pkbf(acc[6], acc[7]));
        float rsd[8];
        #pragma unroll
        for (int q = 0; q < 8; q++)
            rsd[q] = acc[q] - __bfloat162float(__float2bfloat16(acc[q]));
        uint4 lo = make_uint4(pkbf(rsd[0], rsd[1]), pkbf(rsd[2], rsd[3]),
                              pkbf(rsd[4], rsd[5]), pkbf(rsd[6], rsd[7]));
        int s   = lane16 >> 3;
        int gin = lane16 & 7;
        char* dst = buf + s * 4096 + r * 128 + ((gin ^ (r & 7)) * 16);
        *(uint4*)dst = hi;
        *(uint4*)(dst + 16384) = lo;
    }

    // self features cols 128..255: 1024 float4 over 512 threads
    for (int i = tidl; i < 1024; i += 512) {
        int r = i >> 5, c4i = i & 31;
        int c0 = 128 + c4i * 4;
        int row = row0 + r;
        float4 v = make_float4(0.f, 0.f, 0.f, 0.f);
        if (row < n) {
            if (use_x) {
                v = __ldg(&((const float4*)xext)[row * 32 + c4i]);
            } else {
                int cc = c4i * 4;
                v = *(const float4*)(g_hpre + (size_t)row * 128 + cc);
                float4 sc = *(const float4*)(s_sc + cc);
                float4 sh = *(const float4*)(s_sh + cc);
                v.x = fmaxf(v.x * sc.x + sh.x, 0.f);
                v.y = fmaxf(v.y * sc.y + sh.y, 0.f);
                v.z = fmaxf(v.z * sc.z + sh.z, 0.f);
                v.w = fmaxf(v.w * sc.w + sh.w, 0.f);
            }
        }
        float hx = __bfloat162float(__float2bfloat16(v.x));
        float hy = __bfloat162float(__float2bfloat16(v.y));
        float hz = __bfloat162float(__float2bfloat16(v.z));
        float hw2 = __bfloat162float(__float2bfloat16(v.w));
        uint2 hi = make_uint2(pkbf(v.x, v.y), pkbf(v.z, v.w));
        uint2 lo = make_uint2(pkbf(v.x - hx, v.y - hy), pkbf(v.z - hz, v.w - hw2));
        int s   = c0 >> 6;               // 2 or 3
        int cc2 = c0 & 63;
        int gin = cc2 >> 3;
        int hg  = (cc2 >> 2) & 1;
        char* dst = buf + s * 4096 + r * 128 + ((gin ^ (r & 7)) * 16) + hg * 8;
        *(uint2*)dst = hi;
        *(uint2*)(dst + 16384) = lo;
    }
}

// ---------------- consumer: mainloop + epilogue on one 32-row tile ----------
__device__ __forceinline__ void compute_tile(
    int p, int row0, const float* __restrict__ bias, float* stats_out,
    char* smem, uint32_t sb, int n)
{
    int tid = threadIdx.x, wid = tid >> 5, lane = tid & 31;
    int m0 = (wid >> 3) * 16, n0 = (wid & 7) * 16;
    int lx = lane & 7;
    int aRow = lane & 15, aKoff = lane >> 4;
    int wRow = (lane & 7) + ((lane >> 4) << 3), wKoff = (lane >> 3) & 1;
    uint32_t abase = sb + SM_A + p * 32768;
    uint32_t wbase = sb + SM_W;

    float acc[2][4];
    #pragma unroll
    for (int nf = 0; nf < 2; nf++)
        #pragma unroll
        for (int q = 0; q < 4; q++) acc[nf][q] = 0.f;

    #pragma unroll 1
    for (int ks = 0; ks < 16; ks++) {
        int sA = ks >> 2, kg = (ks & 3) * 2;
        uint32_t afh[4], afl[4], wfh[4], wfl[4];
        uint32_t aaddr = abase + sA * 4096 + (m0 + aRow) * 128 +
                         (((kg + aKoff) ^ lx) * 16);
        ldm4(afh, aaddr);
        ldm4(afl, aaddr + 16384);
        uint32_t waddr = wbase + sA * 16384 + (n0 + wRow) * 128 +
                         (((kg + wKoff) ^ lx) * 16);
        ldm4(wfh, waddr);
        ldm4(wfl, waddr + 65536);
        mma16816(acc[0], afh, wfh[0], wfh[1]);
        mma16816(acc[1], afh, wfh[2], wfh[3]);
        mma16816(acc[0], afh, wfl[0], wfl[1]);
        mma16816(acc[1], afh, wfl[2], wfl[3]);
        mma16816(acc[0], afl, wfh[0], wfh[1]);
        mma16816(acc[1], afl, wfh[2], wfh[3]);
    }

    #pragma unroll
    for (int nf = 0; nf < 2; nf++) {
        int col = n0 + nf * 8 + (lane & 3) * 2;
        float bx = __ldg(&bias[col]), by = __ldg(&bias[col + 1]);
        float s0 = 0.f, q0 = 0.f, s1 = 0.f, q1 = 0.f;
        int row = row0 + m0 + (lane >> 2);
        if (row < n) {
            float a = acc[nf][0] + bx, b = acc[nf][1] + by;
            *(float2*)(g_hpre + (size_t)row * 128 + col) = make_float2(a, b);
            s0 += a; q0 += a * a; s1 += b; q1 += b * b;
        }
        if (row + 8 < n) {
            float a = acc[nf][2] + bx, b = acc[nf][3] + by;
            *(float2*)(g_hpre + (size_t)(row + 8) * 128 + col) = make_float2(a, b);
            s0 += a; q0 += a * a; s1 += b; q1 += b * b;
        }
        #pragma unroll
        for (int off = 4; off < 32; off <<= 1) {
            s0 += __shfl_xor_sync(0xffffffffu, s0, off);
            q0 += __shfl_xor_sync(0xffffffffu, q0, off);
            s1 += __shfl_xor_sync(0xffffffffu, s1, off);
            q1 += __shfl_xor_sync(0xffffffffu, q1, off);
        }
        if (lane < 4) {
            int c = n0 + nf * 8 + lane * 2;
            atomicAdd(&stats_out[c],       s0);
            atomicAdd(&stats_out[128 + c], q0);
            atomicAdd(&stats_out[c + 1],       s1);
            atomicAdd(&stats_out[128 + c + 1], q1);
        }
    }
}

// ---------------- pipelined fused aggregate + GEMM phase ----------------
__device__ __forceinline__ void agg_gemm_phase(
    int layer, int use_x, const float* __restrict__ xext,
    const float* __restrict__ bias, const float* s_sc, const float* s_sh,
    char* smem, int* s_cur, int* s_nxt, int n)
{
    uint32_t sb = s2u(smem);
    int tid = threadIdx.x, wid = tid >> 5;
    float* stats_out = layer ? g_stats1 : g_stats0;
    int* tctr = layer ? &g_tile1 : &g_tile0;
    int ntiles = (n + 31) >> 5;

    // load W resident (hi+lo, full K=256): 8192 uint4
    {
        const __nv_bfloat16* wth = g_wth[layer];
        const __nv_bfloat16* wtl = g_wtl[layer];
        for (int i = tid; i < 8192; i += NT) {
            int half = i >> 12, j = i & 4095;
            int r = j >> 5;
            int kin = (j & 31) * 8;
            int s = kin >> 6, gin = (kin >> 3) & 7;
            const __nv_bfloat16* base = half ? wtl : wth;
            uint4 v = __ldg((const uint4*)(base + (size_t)r * 256 + kin));
            *(uint4*)(smem + SM_W + half * 65536 + s * 16384 + r * 128 +
                      ((gin ^ (r & 7)) * 16)) = v;
        }
    }
    if (tid == 0) *s_cur = atomicAdd(tctr, 1);
    __syncthreads();                    // W ready + s_cur visible

    int cur = *s_cur;
    int p = 0;
    if (wid >= 16 && cur < ntiles)
        fill_tile(p, cur << 5, layer, use_x, xext, s_sc, s_sh, smem, n);

    for (;;) {
        __syncthreads();                // buf[p] for cur complete
        if (tid == 0) *s_nxt = (cur < ntiles) ? atomicAdd(tctr, 1) : ntiles;
        __syncthreads();
        int nxt = *s_nxt;
        if (cur >= ntiles) break;
        if (wid < 16)
            compute_tile(p, cur << 5, bias, stats_out, smem, sb, n);
        else if (nxt < ntiles)
            fill_tile(p ^ 1, nxt << 5, layer, use_x, xext, s_sc, s_sh, smem, n);
        cur = nxt;
        p ^= 1;
    }
}

// ---------------- the mega kernel ----------------
__global__ void __launch_bounds__(NT, 1)
k_mega(const float* __restrict__ x, const void* __restrict__ ei,
       const float* __restrict__ Wl0, const float* __restrict__ Wr0,
       const float* __restrict__ b0,
       const float* __restrict__ gm0, const float* __restrict__ be0,
       const float* __restrict__ Wl1, const float* __restrict__ Wr1,
       const float* __restrict__ b1,
       const float* __restrict__ gm1, const float* __restrict__ be1,
       const float* __restrict__ Wout, const float* __restrict__ bout,
       float* __restrict__ out, int E, int n)
{
    extern __shared__ char smem[];
    __shared__ __align__(16) float s_sc[128];
    __shared__ __align__(16) float s_sh[128];
    __shared__ int s_ws[32];
    __shared__ int s_cur, s_nxt;
    int tid  = threadIdx.x, bid = blockIdx.x;
    int gtid = bid * NT + tid;
    int gsz  = gridDim.x * NT;
    int lane = tid & 31, wid = tid >> 5;

    // ---- P0: init ----
    if (gtid == 0) {
        const int* p = (const int*)ei;
        int m = E < 64 ? E : 64, is64 = 1;
        for (int j = 0; j < m; j++)
            if (p[2 * j + 1] != 0) { is64 = 0; break; }
        g_is64 = is64;
        g_tile0 = 0; g_tile1 = 0;
    }
    for (int i = gtid; i < n; i += gsz) { g_deg[i] = 0; g_cursor[i] = 0; }
    if (gtid < 256) { g_stats0[gtid] = 0.f; g_stats1[gtid] = 0.f; }
    gsync();

    // ---- P1: decode edges + degree histogram ----
    {
        int is64 = g_is64;
        for (int i = gtid; i < E; i += gsz) {
            int s, d;
            if (is64) {
                const long long* q = (const long long*)ei;
                s = (int)q[i]; d = (int)q[E + i];
            } else {
                const int* q = (const int*)ei;
                s = q[i]; d = q[E + i];
            }
            g_src[i] = s; g_dst[i] = d;
            atomicAdd(&g_deg[d], 1);
        }
    }
    gsync();

    // ---- P2: per-chunk scan (blocks < sbk) | x->fp16 + W prep (others) ----
    int sbk = (n + 2047) >> 11;
    if (bid < sbk) {
        int i0 = bid * 2048 + tid * 2;
        int v0 = (i0     < n) ? __ldcg(&g_deg[i0])     : 0;
        int v1 = (i0 + 1 < n) ? __ldcg(&g_deg[i0 + 1]) : 0;
        int tot = v0 + v1;
        int xsc = tot;
        #pragma unroll
        for (int off = 1; off < 32; off <<= 1) {
            int t = __shfl_up_sync(0xffffffffu, xsc, off);
            if (lane >= off) xsc += t;
        }
        if (lane == 31) s_ws[wid] = xsc;
        __syncthreads();
        if (wid == 0) {
            int w = s_ws[lane];
            #pragma unroll
            for (int off = 1; off < 32; off <<= 1) {
                int t = __shfl_up_sync(0xffffffffu, w, off);
                if (lane >= off) w += t;
            }
            s_ws[lane] = w;
        }
        __syncthreads();
        int wpref = wid ? s_ws[wid - 1] : 0;
        int incl  = wpref + xsc;
        if (i0     < n) g_rowptr[i0 + 1] = incl - v1;
        if (i0 + 1 < n) g_rowptr[i0 + 2] = incl;
        if (tid == 0) g_bsum[bid] = s_ws[31];
    } else {
        int rb = bid - sbk, nrb = gridDim.x - sbk;
        for (int i = rb * NT + tid; i < n * 32; i += nrb * NT) {
            float4 v = __ldg(&((const float4*)x)[i]);
            __half2 a = __floats2half2_rn(v.x, v.y);
            __half2 b = __floats2half2_rn(v.z, v.w);
            ((uint2*)g_xhalf)[i] = make_uint2(*(uint32_t*)&a, *(uint32_t*)&b);
        }
        for (int i = rb * NT + tid; i < 65536; i += nrb * NT) {
            int layer = i >> 15;
            int t2 = i & 32767;
            int nn = t2 >> 8, k = t2 & 255;
            const float* Wl = layer ? Wl1 : Wl0;
            const float* Wr = layer ? Wr1 : Wr0;
            float v = (k < 128) ? __ldg(&Wl[k * 128 + nn])
                                : __ldg(&Wr[(k - 128) * 128 + nn]);
            __nv_bfloat16 h = __float2bfloat16(v);
            g_wth[layer][t2] = h;
            g_wtl[layer][t2] = __float2bfloat16(v - __bfloat162float(h));
        }
    }
    gsync();

    // ---- P3: scan fixup ----
    for (int i = gtid; i < n; i += gsz) {
        int c = i >> 11, off = 0;
        for (int j = 0; j < c; j++) off += __ldcg(&g_bsum[j]);
        g_rowptr[i + 1] += off;
    }
    if (gtid == 0) g_rowptr[0] = 0;
    gsync();

    // ---- P4: fill sorted edge list ----
    for (int i = gtid; i < E; i += gsz) {
        int d = g_dst[i];
        int p = __ldcg(&g_rowptr[d]) + atomicAdd(&g_cursor[d], 1);
        g_ssort[p] = g_src[i];
    }
    gsync();

    // ---- P5: pipelined agg+GEMM L0 (+stats0) ----
    agg_gemm_phase(0, 1, x, b0, s_sc, s_sh, smem, &s_cur, &s_nxt, n);
    gsync();

    // ---- P6: BN+ReLU -> fp16 ----
    finalize_smem(g_stats0, gm0, be0, n, s_sc, s_sh);
    for (int i = gtid; i < n * 32; i += gsz) {
        int cg = i & 31;
        float4 v  = ((const float4*)g_hpre)[i];
        float4 sc = ((const float4*)s_sc)[cg];
        float4 sh = ((const float4*)s_sh)[cg];
        v.x = fmaxf(v.x * sc.x + sh.x, 0.f);
        v.y = fmaxf(v.y * sc.y + sh.y, 0.f);
        v.z = fmaxf(v.z * sc.z + sh.z, 0.f);
        v.w = fmaxf(v.w * sc.w + sh.w, 0.f);
        __half2 a = __floats2half2_rn(v.x, v.y);
        __half2 b = __floats2half2_rn(v.z, v.w);
        ((uint2*)g_hhalf)[i] = make_uint2(*(uint32_t*)&a, *(uint32_t*)&b);
    }
    gsync();

    // ---- P7: pipelined agg+GEMM L1 (self path uses s_sc/s_sh from P6) ----
    agg_gemm_phase(1, 0, nullptr, b1, s_sc, s_sh, smem, &s_cur, &s_nxt, n);
    gsync();

    // ---- P8: BN+ReLU + [128,2] linear -> out ----
    finalize_smem(g_stats1, gm1, be1, n, s_sc, s_sh);
    for (int node = gtid >> 5; node < n; node += gsz >> 5) {
        float4 v  = __ldcg(&((const float4*)g_hpre)[node * 32 + lane]);
        float4 sc = ((const float4*)s_sc)[lane];
        float4 sh = ((const float4*)s_sh)[lane];
        v.x = fmaxf(v.x * sc.x + sh.x, 0.f);
        v.y = fmaxf(v.y * sc.y + sh.y, 0.f);
        v.z = fmaxf(v.z * sc.z + sh.z, 0.f);
        v.w = fmaxf(v.w * sc.w + sh.w, 0.f);
        const float4* W4 = (const float4*)Wout;
        float4 wa = __ldg(&W4[lane * 2]);
        float4 wb = __ldg(&W4[lane * 2 + 1]);
        float s0 = v.x * wa.x + v.y * wa.z + v.z * wb.x + v.w * wb.z;
        float s1 = v.x * wa.y + v.y * wa.w + v.z * wb.y + v.w * wb.w;
        #pragma unroll
        for (int off = 16; off; off >>= 1) {
            s0 += __shfl_xor_sync(0xffffffffu, s0, off);
            s1 += __shfl_xor_sync(0xffffffffu, s1, off);
        }
        if (lane == 0) {
            out[node * 2 + 0] = s0 + __ldg(&bout[0]);
            out[node * 2 + 1] = s1 + __ldg(&bout[1]);
        }
    }
}

// ---------------------------------------------------------------------------
extern "C" void kernel_launch(void* const* d_in, const int* in_sizes, int n_in,
                              void* d_out, int out_size) {
    const float* x    = (const float*)d_in[0];
    const void*  ei   = d_in[1];
    const float* Wl0  = (const float*)d_in[2];
    const float* Wr0  = (const float*)d_in[3];
    const float* b0   = (const float*)d_in[4];
    const float* gm0  = (const float*)d_in[5];
    const float* be0  = (const float*)d_in[6];
    const float* Wl1  = (const float*)d_in[7];
    const float* Wr1  = (const float*)d_in[8];
    const float* b1   = (const float*)d_in[9];
    const float* gm1  = (const float*)d_in[10];
    const float* be1  = (const float*)d_in[11];
    const float* Wout = (const float*)d_in[12];
    const float* bout = (const float*)d_in[13];
    float* out = (float*)d_out;

    int E = in_sizes[1] / 2;  if (E > MAXE) E = MAXE;
    int n = out_size / 2;     if (n > MAXN) n = MAXN;

    cudaFuncSetAttribute(k_mega,
        cudaFuncAttributeMaxDynamicSharedMemorySize, SM_TOTAL);

    k_mega<<<NB, NT, SM_TOTAL>>>(x, ei, Wl0, Wr0, b0, gm0, be0,
                                 Wl1, Wr1, b1, gm1, be1, Wout, bout,
                                 out, E, n);
}

// round 17
// speedup vs baseline: 1.0654x; 1.0654x over previous
#include <cuda_runtime.h>
#include <cuda_bf16.h>
#include <cuda_fp16.h>
#include <cstdint>

// ---------------------------------------------------------------------------
// GraphSAGE persistent mega-kernel (R15 base; gather uses 4-way edge batching
// for 4x memory-level parallelism). 148 blocks x 1024 threads, grid barriers:
//  P0 init -> P1 edge hist -> P2 scan | x->fp16 + W prep -> P3 scan fixup
//  -> P4 fill -> P5 fused agg+gemm L0 -> P6 bn+relu->fp16
//  -> P7 fused agg+gemm L1 -> P8 bn+relu+linear[128,2] -> out
// 128x128 GEMM tiles from an atomic work queue; each tile gathers its own
// 128 nodes (half-warp x 2 rows; indices batched 4-wide so 4 row gathers are
// in flight per chain) straight into SW128 bf16 hi/lo A smem.
// mma.sync m16n8k16 bf16 split x3; BN stats fused in epilogue.
// ---------------------------------------------------------------------------

#define MAXN 50000
#define MAXE 1048576
#define NB 148
#define NT 1024

__device__ float g_hpre[MAXN * 128];
__device__ __half g_xhalf[MAXN * 128];
__device__ __half g_hhalf[MAXN * 128];
__device__ __nv_bfloat16 g_wth [2][128 * 256];
__device__ __nv_bfloat16 g_wtl [2][128 * 256];
__device__ int   g_deg   [MAXN];
__device__ int   g_rowptr[MAXN + 1];
__device__ int   g_cursor[MAXN];
__device__ int   g_src   [MAXE];
__device__ int   g_dst   [MAXE];
__device__ int   g_ssort [MAXE];
__device__ int   g_bsum  [32];
__device__ float g_stats0[256];
__device__ float g_stats1[256];
__device__ int   g_tile0, g_tile1;
__device__ int   g_is64;
__device__ int   g_barc = 0;
__device__ volatile int g_barp = 0;

// ---------------- helpers ----------------
__device__ __forceinline__ uint32_t s2u(const void* p) {
    uint32_t a;
    asm("{ .reg .u64 t; cvta.to.shared.u64 t, %1; cvt.u32.u64 %0, t; }"
        : "=r"(a) : "l"(p));
    return a;
}
__device__ __forceinline__ void ldm4(uint32_t* r, uint32_t addr) {
    asm volatile("ldmatrix.sync.aligned.m8n8.x4.shared.b16 {%0,%1,%2,%3}, [%4];"
        : "=r"(r[0]), "=r"(r[1]), "=r"(r[2]), "=r"(r[3]) : "r"(addr));
}
__device__ __forceinline__ void mma16816(float* d, const uint32_t* a,
                                         uint32_t b0, uint32_t b1) {
    asm volatile(
        "mma.sync.aligned.m16n8k16.row.col.f32.bf16.bf16.f32 "
        "{%0,%1,%2,%3}, {%4,%5,%6,%7}, {%8,%9}, {%0,%1,%2,%3};"
        : "+f"(d[0]), "+f"(d[1]), "+f"(d[2]), "+f"(d[3])
        : "r"(a[0]), "r"(a[1]), "r"(a[2]), "r"(a[3]), "r"(b0), "r"(b1));
}
__device__ __forceinline__ uint32_t pkbf(float a, float b) {
    __nv_bfloat162 h = __halves2bfloat162(__float2bfloat16(a), __float2bfloat16(b));
    return *(uint32_t*)&h;
}
__device__ __forceinline__ void addrow(float* acc, uint4 p) {
    const __half2* h = (const __half2*)&p;
    #pragma unroll
    for (int q = 0; q < 4; q++) {
        float2 f = __half22float2(h[q]);
        acc[2 * q]     += f.x;
        acc[2 * q + 1] += f.y;
    }
}

// grid-wide barrier (all NB blocks resident by construction)
__device__ __forceinline__ void gsync() {
    __syncthreads();
    if (threadIdx.x == 0) {
        __threadfence();
        int gen = g_barp;
        if (atomicAdd(&g_barc, 1) == (int)gridDim.x - 1) {
            g_barc = 0;
            __threadfence();
            g_barp = gen + 1;
        } else {
            while (g_barp == gen) __nanosleep(32);
            __threadfence();
        }
    }
    __syncthreads();
}

// BN finalize from raw stats into smem scale/shift
__device__ __forceinline__ void finalize_smem(
        const float* __restrict__ stats, const float* __restrict__ gamma,
        const float* __restrict__ beta, int n, float* s_sc, float* s_sh) {
    int t = threadIdx.x;
    if (t < 128) {
        float invn = 1.0f / (float)n;
        float mu  = __ldcg(&stats[t]) * invn;
        float var = fmaxf(__ldcg(&stats[128 + t]) * invn - mu * mu, 0.f);
        float rs  = rsqrtf(var + 1e-5f);
        float sc  = __ldg(&gamma[t]) * rs;
        s_sc[t] = sc;
        s_sh[t] = __ldg(&beta[t]) - mu * sc;
    }
    __syncthreads();
}

// smem layout (dynamic)
#define SM_A  0            // A: 2 halves x 4 k-sections x [128r][64c bf16] = 131072
#define SM_W  131072       // W chunk: 2 halves x 2 k-sections x [128n][64k] = 65536
#define SM_TOTAL 196608

// ---------------- fused aggregate + GEMM phase ----------------
__device__ __forceinline__ void agg_gemm_phase(
    int layer, int use_x, const float* __restrict__ xext,
    const float* __restrict__ bias, const float* s_sc, const float* s_sh,
    char* smem, int* s_tile, int n)
{
    uint32_t sb = s2u(smem);
    int tid = threadIdx.x, wid = tid >> 5, lane = tid & 31;
    int hw = tid >> 4, lane16 = tid & 15;
    float* stats_out = layer ? g_stats1 : g_stats0;
    int* tctr = layer ? &g_tile1 : &g_tile0;
    const __nv_bfloat16* wth = g_wth[layer];
    const __nv_bfloat16* wtl = g_wtl[layer];
    const uint4* gin4 = (const uint4*)(layer ? g_hhalf : g_xhalf);
    int wm = wid >> 3, wn = wid & 7;
    int m0 = wm * 32, n0 = wn * 16;
    int lx = lane & 7;
    int aRow = lane & 15, aKoff = lane >> 4;
    int wRow = (lane & 7) + ((lane >> 4) << 3), wKoff = (lane >> 3) & 1;
    int ntiles = (n + 127) >> 7;

    for (;;) {
        __syncthreads();   // prior tile's mainloop done before A overwrite
        if (tid == 0) *s_tile = atomicAdd(tctr, 1);
        __syncthreads();
        int t = *s_tile;
        if (t >= ntiles) break;
        int row0 = t << 7;

        // ---- fused aggregation: cols 0..127 of A, 4-way edge batching ----
        #pragma unroll 1
        for (int rr = 0; rr < 128; rr += 64) {
            int r = hw + rr;
            int node = row0 + r;
            float acc[8] = {0.f, 0.f, 0.f, 0.f, 0.f, 0.f, 0.f, 0.f};
            if (node < n) {
                int e0 = __ldcg(&g_rowptr[node]);
                int e1 = __ldcg(&g_rowptr[node + 1]);
                int e = e0;
                #pragma unroll 1
                for (; e + 4 <= e1; e += 4) {
                    int sa = __ldg(&g_ssort[e]);
                    int sb2 = __ldg(&g_ssort[e + 1]);
                    int sc2 = __ldg(&g_ssort[e + 2]);
                    int sd2 = __ldg(&g_ssort[e + 3]);
                    uint4 pa = __ldg(&gin4[sa * 16 + lane16]);
                    uint4 pb = __ldg(&gin4[sb2 * 16 + lane16]);
                    uint4 pc = __ldg(&gin4[sc2 * 16 + lane16]);
                    uint4 pd = __ldg(&gin4[sd2 * 16 + lane16]);
                    addrow(acc, pa);
                    addrow(acc, pb);
                    addrow(acc, pc);
                    addrow(acc, pd);
                }
                #pragma unroll 1
                for (; e < e1; e++) {
                    int sa = __ldg(&g_ssort[e]);
                    uint4 pa = __ldg(&gin4[sa * 16 + lane16]);
                    addrow(acc, pa);
                }
                float inv = 1.0f / fmaxf((float)(e1 - e0), 1.0f);
                #pragma unroll
                for (int q = 0; q < 8; q++) acc[q] *= inv;
            }
            uint4 hi = make_uint4(pkbf(acc[0], acc[1]), pkbf(acc[2], acc[3]),
                                  pkbf(acc[4], acc[5]), pkbf(acc[6], acc[7]));
            float rsd[8];
            #pragma unroll
            for (int q = 0; q < 8; q++)
                rsd[q] = acc[q] - __bfloat162float(__float2bfloat16(acc[q]));
            uint4 lo = make_uint4(pkbf(rsd[0], rsd[1]), pkbf(rsd[2], rsd[3]),
                                  pkbf(rsd[4], rsd[5]), pkbf(rsd[6], rsd[7]));
            int s   = lane16 >> 3;
            int gin = lane16 & 7;
            char* dst = smem + SM_A + s * 16384 + r * 128 + ((gin ^ (r & 7)) * 16);
            *(uint4*)dst = hi;
            *(uint4*)(dst + 65536) = lo;
        }

        // ---- self features: cols 128..255 of A ----
        for (int i = tid; i < 4096; i += NT) {
            int r = i >> 5, c4i = i & 31;
            int c0 = 128 + c4i * 4;
            int row = row0 + r;
            float4 v = make_float4(0.f, 0.f, 0.f, 0.f);
            if (row < n) {
                if (use_x) {
                    v = __ldg(&((const float4*)xext)[row * 32 + c4i]);
                } else {
                    int cc = c4i * 4;
                    v = *(const float4*)(g_hpre + (size_t)row * 128 + cc);
                    float4 sc = *(const float4*)(s_sc + cc);
                    float4 sh = *(const float4*)(s_sh + cc);
                    v.x = fmaxf(v.x * sc.x + sh.x, 0.f);
                    v.y = fmaxf(v.y * sc.y + sh.y, 0.f);
                    v.z = fmaxf(v.z * sc.z + sh.z, 0.f);
                    v.w = fmaxf(v.w * sc.w + sh.w, 0.f);
                }
            }
            float hx = __bfloat162float(__float2bfloat16(v.x));
            float hy = __bfloat162float(__float2bfloat16(v.y));
            float hz = __bfloat162float(__float2bfloat16(v.z));
            float hw2 = __bfloat162float(__float2bfloat16(v.w));
            uint2 hi = make_uint2(pkbf(v.x, v.y), pkbf(v.z, v.w));
            uint2 lo = make_uint2(pkbf(v.x - hx, v.y - hy), pkbf(v.z - hz, v.w - hw2));
            int s   = c0 >> 6;
            int cc2 = c0 & 63;
            int gin = cc2 >> 3;
            int hg  = (cc2 >> 2) & 1;
            char* dst = smem + SM_A + s * 16384 + r * 128 +
                        ((gin ^ (r & 7)) * 16) + hg * 8;
            *(uint2*)dst = hi;
            *(uint2*)(dst + 65536) = lo;
        }

        float acc[2][2][4];
        #pragma unroll
        for (int mf = 0; mf < 2; mf++)
            #pragma unroll
            for (int nf = 0; nf < 2; nf++)
                #pragma unroll
                for (int q = 0; q < 4; q++) acc[mf][nf][q] = 0.f;

        #pragma unroll 1
        for (int kc = 0; kc < 2; kc++) {
            __syncthreads();
            // ---- W chunk (hi + lo) ----
            for (int i = tid; i < 4096; i += NT) {
                int half = i >> 11;
                int j = i & 2047;
                int r = j >> 4;
                int kin = (j & 15) * 8;
                int s2 = kin >> 6;
                int gin = (kin >> 3) & 7;
                const __nv_bfloat16* base = half ? wtl : wth;
                uint4 v = __ldg((const uint4*)(base + (size_t)r * 256 + kc * 128 + kin));
                *(uint4*)(smem + SM_W + half * 32768 + s2 * 16384 + r * 128 +
                          ((gin ^ (r & 7)) * 16)) = v;
            }
            __syncthreads();

            #pragma unroll 1
            for (int ksl = 0; ksl < 8; ksl++) {
                int ks  = kc * 8 + ksl;
                int sA  = ks >> 2;
                int kgA = (ks & 3) * 2 + aKoff;
                int s2  = ksl >> 2;
                int kgW = (ksl & 3) * 2 + wKoff;
                uint32_t wfh[4], wfl[4];
                {
                    int r = n0 + wRow;
                    uint32_t a = sb + SM_W + s2 * 16384 + r * 128 + ((kgW ^ lx) * 16);
                    ldm4(wfh, a);
                    ldm4(wfl, a + 32768);
                }
                #pragma unroll
                for (int ah = 0; ah < 2; ah++) {
                    uint32_t af[2][4];
                    #pragma unroll
                    for (int mf = 0; mf < 2; mf++) {
                        int r = m0 + mf * 16 + aRow;
                        ldm4(af[mf], sb + SM_A + ah * 65536 + sA * 16384 +
                                     r * 128 + ((kgA ^ lx) * 16));
                    }
                    #pragma unroll
                    for (int mf = 0; mf < 2; mf++) {
                        mma16816(acc[mf][0], af[mf], wfh[0], wfh[1]);
                        mma16816(acc[mf][1], af[mf], wfh[2], wfh[3]);
                    }
                    if (ah == 0) {
                        #pragma unroll
                        for (int mf = 0; mf < 2; mf++) {
                            mma16816(acc[mf][0], af[mf], wfl[0], wfl[1]);
                            mma16816(acc[mf][1], af[mf], wfl[2], wfl[3]);
                        }
                    }
                }
            }
        }

        // ---- epilogue: bias, store fp32, fused BN stats ----
        #pragma unroll
        for (int nf = 0; nf < 2; nf++) {
            int col = n0 + nf * 8 + (lane & 3) * 2;
            float bx = __ldg(&bias[col]), by = __ldg(&bias[col + 1]);
            float s0 = 0.f, q0 = 0.f, s1 = 0.f, q1 = 0.f;
            #pragma unroll
            for (int mf = 0; mf < 2; mf++) {
                int row = row0 + m0 + mf * 16 + (lane >> 2);
                if (row < n) {
                    float a = acc[mf][nf][0] + bx, b = acc[mf][nf][1] + by;
                    *(float2*)(g_hpre + (size_t)row * 128 + col) = make_float2(a, b);
                    s0 += a; q0 += a * a; s1 += b; q1 += b * b;
                }
                if (row + 8 < n) {
                    float a = acc[mf][nf][2] + bx, b = acc[mf][nf][3] + by;
                    *(float2*)(g_hpre + (size_t)(row + 8) * 128 + col) = make_float2(a, b);
                    s0 += a; q0 += a * a; s1 += b; q1 += b * b;
                }
            }
            #pragma unroll
            for (int off = 4; off < 32; off <<= 1) {
                s0 += __shfl_xor_sync(0xffffffffu, s0, off);
                q0 += __shfl_xor_sync(0xffffffffu, q0, off);
                s1 += __shfl_xor_sync(0xffffffffu, s1, off);
                q1 += __shfl_xor_sync(0xffffffffu, q1, off);
            }
            if (lane < 4) {
                int c = n0 + nf * 8 + lane * 2;
                atomicAdd(&stats_out[c],       s0);
                atomicAdd(&stats_out[128 + c], q0);
                atomicAdd(&stats_out[c + 1],       s1);
                atomicAdd(&stats_out[128 + c + 1], q1);
            }
        }
    }
}

// ---------------- the mega kernel ----------------
__global__ void __launch_bounds__(NT, 1)
k_mega(const float* __restrict__ x, const void* __restrict__ ei,
       const float* __restrict__ Wl0, const float* __restrict__ Wr0,
       const float* __restrict__ b0,
       const float* __restrict__ gm0, const float* __restrict__ be0,
       const float* __restrict__ Wl1, const float* __restrict__ Wr1,
       const float* __restrict__ b1,
       const float* __restrict__ gm1, const float* __restrict__ be1,
       const float* __restrict__ Wout, const float* __restrict__ bout,
       float* __restrict__ out, int E, int n)
{
    extern __shared__ char smem[];
    __shared__ __align__(16) float s_sc[128];
    __shared__ __align__(16) float s_sh[128];
    __shared__ int s_ws[32];
    __shared__ int s_tile;
    int tid  = threadIdx.x, bid = blockIdx.x;
    int gtid = bid * NT + tid;
    int gsz  = gridDim.x * NT;
    int lane = tid & 31, wid = tid >> 5;

    // ---- P0: init ----
    if (gtid == 0) {
        const int* p = (const int*)ei;
        int m = E < 64 ? E : 64, is64 = 1;
        for (int j = 0; j < m; j++)
            if (p[2 * j + 1] != 0) { is64 = 0; break; }
        g_is64 = is64;
        g_tile0 = 0; g_tile1 = 0;
    }
    for (int i = gtid; i < n; i += gsz) { g_deg[i] = 0; g_cursor[i] = 0; }
    if (gtid < 256) { g_stats0[gtid] = 0.f; g_stats1[gtid] = 0.f; }
    gsync();

    // ---- P1: decode edges + degree histogram ----
    {
        int is64 = g_is64;
        for (int i = gtid; i < E; i += gsz) {
            int s, d;
            if (is64) {
                const long long* q = (const long long*)ei;
                s = (int)q[i]; d = (int)q[E + i];
            } else {
                const int* q = (const int*)ei;
                s = q[i]; d = q[E + i];
            }
            g_src[i] = s; g_dst[i] = d;
            atomicAdd(&g_deg[d], 1);
        }
    }
    gsync();

    // ---- P2: per-chunk scan (blocks < sbk) | x->fp16 + W prep (others) ----
    int sbk = (n + 2047) >> 11;
    if (bid < sbk) {
        int i0 = bid * 2048 + tid * 2;
        int v0 = (i0     < n) ? __ldcg(&g_deg[i0])     : 0;
        int v1 = (i0 + 1 < n) ? __ldcg(&g_deg[i0 + 1]) : 0;
        int tot = v0 + v1;
        int xsc = tot;
        #pragma unroll
        for (int off = 1; off < 32; off <<= 1) {
            int t = __shfl_up_sync(0xffffffffu, xsc, off);
            if (lane >= off) xsc += t;
        }
        if (lane == 31) s_ws[wid] = xsc;
        __syncthreads();
        if (wid == 0) {
            int w = s_ws[lane];
            #pragma unroll
            for (int off = 1; off < 32; off <<= 1) {
                int t = __shfl_up_sync(0xffffffffu, w, off);
                if (lane >= off) w += t;
            }
            s_ws[lane] = w;
        }
        __syncthreads();
        int wpref = wid ? s_ws[wid - 1] : 0;
        int incl  = wpref + xsc;
        if (i0     < n) g_rowptr[i0 + 1] = incl - v1;
        if (i0 + 1 < n) g_rowptr[i0 + 2] = incl;
        if (tid == 0) g_bsum[bid] = s_ws[31];
    } else {
        int rb = bid - sbk, nrb = gridDim.x - sbk;
        for (int i = rb * NT + tid; i < n * 32; i += nrb * NT) {
            float4 v = __ldg(&((const float4*)x)[i]);
            __half2 a = __floats2half2_rn(v.x, v.y);
            __half2 b = __floats2half2_rn(v.z, v.w);
            ((uint2*)g_xhalf)[i] = make_uint2(*(uint32_t*)&a, *(uint32_t*)&b);
        }
        for (int i = rb * NT + tid; i < 65536; i += nrb * NT) {
            int layer = i >> 15;
            int t2 = i & 32767;
            int nn = t2 >> 8, k = t2 & 255;
            const float* Wl = layer ? Wl1 : Wl0;
            const float* Wr = layer ? Wr1 : Wr0;
            float v = (k < 128) ? __ldg(&Wl[k * 128 + nn])
                                : __ldg(&Wr[(k - 128) * 128 + nn]);
            __nv_bfloat16 h = __float2bfloat16(v);
            g_wth[layer][t2] = h;
            g_wtl[layer][t2] = __float2bfloat16(v - __bfloat162float(h));
        }
    }
    gsync();

    // ---- P3: scan fixup ----
    for (int i = gtid; i < n; i += gsz) {
        int c = i >> 11, off = 0;
        for (int j = 0; j < c; j++) off += __ldcg(&g_bsum[j]);
        g_rowptr[i + 1] += off;
    }
    if (gtid == 0) g_rowptr[0] = 0;
    gsync();

    // ---- P4: fill sorted edge list ----
    for (int i = gtid; i < E; i += gsz) {
        int d = g_dst[i];
        int p = __ldcg(&g_rowptr[d]) + atomicAdd(&g_cursor[d], 1);
        g_ssort[p] = g_src[i];
    }
    gsync();

    // ---- P5: fused agg+GEMM L0 (+stats0) ----
    agg_gemm_phase(0, 1, x, b0, s_sc, s_sh, smem, &s_tile, n);
    gsync();

    // ---- P6: BN+ReLU -> fp16 ----
    finalize_smem(g_stats0, gm0, be0, n, s_sc, s_sh);
    for (int i = gtid; i < n * 32; i += gsz) {
        int cg = i & 31;
        float4 v  = ((const float4*)g_hpre)[i];
        float4 sc = ((const float4*)s_sc)[cg];
        float4 sh = ((const float4*)s_sh)[cg];
        v.x = fmaxf(v.x * sc.x + sh.x, 0.f);
        v.y = fmaxf(v.y * sc.y + sh.y, 0.f);
        v.z = fmaxf(v.z * sc.z + sh.z, 0.f);
        v.w = fmaxf(v.w * sc.w + sh.w, 0.f);
        __half2 a = __floats2half2_rn(v.x, v.y);
        __half2 b = __floats2half2_rn(v.z, v.w);
        ((uint2*)g_hhalf)[i] = make_uint2(*(uint32_t*)&a, *(uint32_t*)&b);
    }
    gsync();

    // ---- P7: fused agg+GEMM L1 (self path uses s_sc/s_sh from P6) ----
    agg_gemm_phase(1, 0, nullptr, b1, s_sc, s_sh, smem, &s_tile, n);
    gsync();

    // ---- P8: BN+ReLU + [128,2] linear -> out ----
    finalize_smem(g_stats1, gm1, be1, n, s_sc, s_sh);
    for (int node = gtid >> 5; node < n; node += gsz >> 5) {
        float4 v  = __ldcg(&((const float4*)g_hpre)[node * 32 + lane]);
        float4 sc = ((const float4*)s_sc)[lane];
        float4 sh = ((const float4*)s_sh)[lane];
        v.x = fmaxf(v.x * sc.x + sh.x, 0.f);
        v.y = fmaxf(v.y * sc.y + sh.y, 0.f);
        v.z = fmaxf(v.z * sc.z + sh.z, 0.f);
        v.w = fmaxf(v.w * sc.w + sh.w, 0.f);
        const float4* W4 = (const float4*)Wout;
        float4 wa = __ldg(&W4[lane * 2]);
        float4 wb = __ldg(&W4[lane * 2 + 1]);
        float s0 = v.x * wa.x + v.y * wa.z + v.z * wb.x + v.w * wb.z;
        float s1 = v.x * wa.y + v.y * wa.w + v.z * wb.y + v.w * wb.w;
        #pragma unroll
        for (int off = 16; off; off >>= 1) {
            s0 += __shfl_xor_sync(0xffffffffu, s0, off);
            s1 += __shfl_xor_sync(0xffffffffu, s1, off);
        }
        if (lane == 0) {
            out[node * 2 + 0] = s0 + __ldg(&bout[0]);
            out[node * 2 + 1] = s1 + __ldg(&bout[1]);
        }
    }
}

// ---------------------------------------------------------------------------
extern "C" void kernel_launch(void* const* d_in, const int* in_sizes, int n_in,
                              void* d_out, int out_size) {
    const float* x    = (const float*)d_in[0];
    const void*  ei   = d_in[1];
    const float* Wl0  = (const float*)d_in[2];
    const float* Wr0  = (const float*)d_in[3];
    const float* b0   = (const float*)d_in[4];
    const float* gm0  = (const float*)d_in[5];
    const float* be0  = (const float*)d_in[6];
    const float* Wl1  = (const float*)d_in[7];
    const float* Wr1  = (const float*)d_in[8];
    const float* b1   = (const float*)d_in[9];
    const float* gm1  = (const float*)d_in[10];
    const float* be1  = (const float*)d_in[11];
    const float* Wout = (const float*)d_in[12];
    const float* bout = (const float*)d_in[13];
    float* out = (float*)d_out;

    int E = in_sizes[1] / 2;  if (E > MAXE) E = MAXE;
    int n = out_size / 2;     if (n > MAXN) n = MAXN;

    cudaFuncSetAttribute(k_mega,
        cudaFuncAttributeMaxDynamicSharedMemorySize, SM_TOTAL);

    k_mega<<<NB, NT, SM_TOTAL>>>(x, ei, Wl0, Wr0, b0, gm0, be0,
                                 Wl1, Wr1, b1, gm1, be1, Wout, bout,
                                 out, E, n);
}